// round 15
// baseline (speedup 1.0000x reference)
#include <cuda_runtime.h>
#include <cstdint>

#define TOKENS 2048
#define NDIM 4096
#define MDIM 4096
#define SP 2048
#define EPSV 1e-8f

#define BM 128
#define BN 256
#define BK 32
#define NSTAGES 4
#define NTHREADS 256

#define A_WORDS (BM * BK)                 // 4096
#define B_WORDS (BN * BK)                 // 8192
#define STAGE_WORDS (A_WORDS + B_WORDS)   // 12288 = 48KB
#define COEF_WORDS (BN + BN + BN / 2 + BN / 2)
#define SMEM_BYTES ((NSTAGES * STAGE_WORDS + COEF_WORDS) * 4)  // ~195.5KB

// Scratch (device globals; runtime allocation forbidden)
__device__ float g_Wr[(size_t)NDIM * MDIM];   // RNA-rounded W
__device__ float g_y[(size_t)TOKENS * MDIM];  // RNA-rounded right-rotated x
__device__ float g_cL[SP], g_sL[SP], g_cR[SP], g_sR[SP];
__device__ float g_scale[NDIM];

// ---------------------------------------------------------------------------
__device__ __forceinline__ uint32_t f2tf32(float x) {
    uint32_t u;
    asm("cvt.rna.tf32.f32 %0, %1;" : "=r"(u) : "f"(x));
    return u;
}
__device__ __forceinline__ float4 rnd4(float4 a) {
    float4 r;
    r.x = __uint_as_float(f2tf32(a.x)); r.y = __uint_as_float(f2tf32(a.y));
    r.z = __uint_as_float(f2tf32(a.z)); r.w = __uint_as_float(f2tf32(a.w));
    return r;
}
__device__ __forceinline__ uint32_t smem_u32(const void* p) {
    uint32_t a;
    asm("{ .reg .u64 t; cvta.to.shared.u64 t, %1; cvt.u32.u64 %0, t; }" : "=r"(a) : "l"(p));
    return a;
}
__device__ __forceinline__ void cpa16(uint32_t dst, const float* src) {
    asm volatile("cp.async.cg.shared.global [%0], [%1], 16;" :: "r"(dst), "l"(src) : "memory");
}
#define CP_COMMIT() asm volatile("cp.async.commit_group;" ::: "memory")
#define CP_WAIT2()  asm volatile("cp.async.wait_group 2;" ::: "memory")

__device__ __forceinline__ void mma_tf32(float* c, const uint32_t* a, const uint32_t* b) {
    asm volatile(
        "mma.sync.aligned.m16n8k8.row.col.f32.tf32.tf32.f32 "
        "{%0,%1,%2,%3}, {%4,%5,%6,%7}, {%8,%9}, {%0,%1,%2,%3};\n"
        : "+f"(c[0]), "+f"(c[1]), "+f"(c[2]), "+f"(c[3])
        : "r"(a[0]), "r"(a[1]), "r"(a[2]), "r"(a[3]), "r"(b[0]), "r"(b[1]));
}
__device__ __forceinline__ void ldsm4(uint32_t& r0, uint32_t& r1, uint32_t& r2,
                                      uint32_t& r3, uint32_t addr) {
    asm volatile(
        "ldmatrix.sync.aligned.m8n8.x4.shared.b16 {%0,%1,%2,%3}, [%4];"
        : "=r"(r0), "=r"(r1), "=r"(r2), "=r"(r3) : "r"(addr));
}

// ---------------------------------------------------------------------------
// Kernel 1: per-pair row scales + RNA-rounded W copy + sincos, one pass.
// Block k handles pair (2k, 2k+1). Single-shot layout: 256 threads x 16
// floats = the full 4096-col row pair; 8 independent float4 loads per
// thread (MLP 8) with streaming __ldcs/__stcs (W touched exactly once).
// ---------------------------------------------------------------------------
__global__ __launch_bounds__(256) void scale_kernel(
    const float* __restrict__ W, const float* __restrict__ ecd,
    const float* __restrict__ thL, const float* __restrict__ thR) {
    int k = blockIdx.x;
    int i = 2 * k, j = 2 * k + 1;
    if (threadIdx.x == 32) {
        g_cR[k] = cosf(thR[k]);
        g_sR[k] = sinf(thR[k]);
    }
    const float4* ri = (const float4*)(W + (size_t)i * MDIM) + threadIdx.x * 4;
    const float4* rj = (const float4*)(W + (size_t)j * MDIM) + threadIdx.x * 4;
    float4* wi = (float4*)(g_Wr + (size_t)i * MDIM) + threadIdx.x * 4;
    float4* wj = (float4*)(g_Wr + (size_t)j * MDIM) + threadIdx.x * 4;

    float4 a[4], b[4];
    #pragma unroll
    for (int q = 0; q < 4; q++) a[q] = __ldcs(ri + q);
    #pragma unroll
    for (int q = 0; q < 4; q++) b[q] = __ldcs(rj + q);

    float ni = 0.f, nj = 0.f, dd = 0.f;
    #pragma unroll
    for (int q = 0; q < 4; q++) {
        ni += a[q].x * a[q].x + a[q].y * a[q].y + a[q].z * a[q].z + a[q].w * a[q].w;
        nj += b[q].x * b[q].x + b[q].y * b[q].y + b[q].z * b[q].z + b[q].w * b[q].w;
        dd += a[q].x * b[q].x + a[q].y * b[q].y + a[q].z * b[q].z + a[q].w * b[q].w;
        __stcs(wi + q, rnd4(a[q]));
        __stcs(wj + q, rnd4(b[q]));
    }
    #pragma unroll
    for (int off = 16; off; off >>= 1) {
        ni += __shfl_down_sync(0xFFFFFFFFu, ni, off);
        nj += __shfl_down_sync(0xFFFFFFFFu, nj, off);
        dd += __shfl_down_sync(0xFFFFFFFFu, dd, off);
    }
    __shared__ float sm[3][8];
    int w = threadIdx.x >> 5;
    if ((threadIdx.x & 31) == 0) { sm[0][w] = ni; sm[1][w] = nj; sm[2][w] = dd; }
    __syncthreads();
    if (threadIdx.x == 0) {
        ni = 0.f; nj = 0.f; dd = 0.f;
        #pragma unroll
        for (int q = 0; q < 8; q++) { ni += sm[0][q]; nj += sm[1][q]; dd += sm[2][q]; }
        float c = cosf(thL[k]), s = sinf(thL[k]);
        g_cL[k] = c; g_sL[k] = s;
        float ri2 = c * c * ni + s * s * nj - 2.f * c * s * dd;
        float rj2 = s * s * ni + c * c * nj + 2.f * c * s * dd;
        g_scale[i] = sqrtf(ni) * expf(ecd[i]) / (sqrtf(fmaxf(ri2, 0.f)) + EPSV);
        g_scale[j] = sqrtf(nj) * expf(ecd[j]) / (sqrtf(fmaxf(rj2, 0.f)) + EPSV);
    }
}

// ---------------------------------------------------------------------------
// Kernel 2: y = right-rotate(x) with RNA rounding.
// ---------------------------------------------------------------------------
__global__ __launch_bounds__(256) void xrot_kernel(const float* __restrict__ x) {
    int idx = blockIdx.x * blockDim.x + threadIdx.x;   // per float4
    int c4 = (idx * 4) & (MDIM - 1);
    int b0 = c4 >> 1;
    float4 v = *(const float4*)(x + (size_t)idx * 4);
    float c0 = g_cR[b0], s0 = g_sR[b0];
    float c1 = g_cR[b0 + 1], s1 = g_sR[b0 + 1];
    float4 o;
    o.x = __uint_as_float(f2tf32(c0 * v.x + s0 * v.y));
    o.y = __uint_as_float(f2tf32(-s0 * v.x + c0 * v.y));
    o.z = __uint_as_float(f2tf32(c1 * v.z + s1 * v.w));
    o.w = __uint_as_float(f2tf32(-s1 * v.z + c1 * v.w));
    *(float4*)(g_y + (size_t)idx * 4) = o;
}

// ---------------------------------------------------------------------------
// Kernel 3: GEMM out = epilogue( y @ Wr^T ).
// CTA 128x256, BK=32, 256 threads: 8 warps in 2x4, warp tile 64x64.
// 4-stage cp.async pipeline (48KB/stage = 192KB), wait_group 2 (stage
// consumed was committed 3 iterations earlier). The 12 cp.async per
// iteration are split across ks=0 (A + half of B) and ks=1 (rest of B +
// commit) to halve the post-barrier LSU burst colliding with LDSM.
// Fragments via ldmatrix.m8n8.x4.b16; XOR swizzle within 32-word rows.
// Epilogue: left rotation over adjacent output col pairs + scale + bias.
// ---------------------------------------------------------------------------
__global__ __launch_bounds__(NTHREADS, 1) void gemm_kernel(
    const float* __restrict__ bias, float* __restrict__ out) {
    extern __shared__ uint32_t smw[];
    float* scale_s = (float*)(smw + NSTAGES * STAGE_WORDS);
    float* bias_s = scale_s + BN;
    float* cL_s = bias_s + BN;
    float* sL_s = cL_s + BN / 2;

    int tid = threadIdx.x;
    int bm = blockIdx.y * BM;
    int bn = blockIdx.x * BN;

    // stage epilogue coefficients (visible after first __syncthreads in loop)
    {
        scale_s[tid] = g_scale[bn + tid];
        bias_s[tid] = bias[bn + tid];
        if (tid < BN / 2) {
            cL_s[tid] = g_cL[(bn >> 1) + tid];
            sL_s[tid] = g_sL[(bn >> 1) + tid];
        }
    }

    // loader mapping: 32 rows x 8 x 16B per round (A: 4 rounds, B: 8 rounds)
    int lrow = tid >> 3;              // 0..31
    int lc4 = (tid & 7) * 4;          // 0..28
    int stx = lc4 ^ ((lrow & 7) * 4); // swizzled word offset within 32-word row
    uint32_t sw = smem_u32(smw);

    const float* ybase = g_y + (size_t)(bm + lrow) * MDIM + lc4;
    const float* wbase = g_Wr + (size_t)(bn + lrow) * MDIM + lc4;

    int warp = tid >> 5, lane = tid & 31;
    int g = lane >> 2, t = lane & 3;
    int wm = (warp >> 2) * 64;        // 0,64
    int wn = (warp & 3) * 64;         // 0,64,128,192

    // ldmatrix lane-address precompute
    int sub = lane >> 3, r = lane & 7;
    int swz = 4 * r;
    int aKoff = (sub >> 1) * 4;
    int bKoff = (sub & 1) * 4;
    uint32_t aBase[4], bBase[4];
    {
        int aRow = wm + (sub & 1) * 8 + r;
        #pragma unroll
        for (int mi = 0; mi < 4; mi++)
            aBase[mi] = (uint32_t)(aRow + 16 * mi) * (BK * 4);
        int bGrp = sub >> 1;               // 0 or 1
        #pragma unroll
        for (int p = 0; p < 4; p++)
            bBase[p] = (uint32_t)(wn + 8 * (2 * p + bGrp) + r) * (BK * 4);
    }

    float acc[4][8][4];
    #pragma unroll
    for (int mi = 0; mi < 4; mi++)
        #pragma unroll
        for (int ni = 0; ni < 8; ni++)
            #pragma unroll
            for (int q = 0; q < 4; q++) acc[mi][ni][q] = 0.f;

    const int NKT = MDIM / BK;  // 128

    // prologue: stages 0..2
    #pragma unroll
    for (int s = 0; s < NSTAGES - 1; s++) {
        uint32_t da = sw + (s * STAGE_WORDS + lrow * BK + stx) * 4;
        #pragma unroll
        for (int it = 0; it < 4; it++)
            cpa16(da + it * (32 * BK * 4), ybase + s * BK + (size_t)it * 32 * MDIM);
        uint32_t db = sw + (s * STAGE_WORDS + A_WORDS + lrow * BK + stx) * 4;
        #pragma unroll
        for (int it = 0; it < 8; it++)
            cpa16(db + it * (32 * BK * 4), wbase + s * BK + (size_t)it * 32 * MDIM);
        CP_COMMIT();
    }

    int sc = 0, sl = NSTAGES - 1;
    #pragma unroll 1
    for (int kt = 0; kt < NKT; kt++) {
        CP_WAIT2();
        __syncthreads();

        uint32_t sA = sw + (uint32_t)sc * (STAGE_WORDS * 4);
        uint32_t sB = sA + A_WORDS * 4;
        int nk = kt + NSTAGES - 1;
        bool doLoad = (nk < NKT);
        uint32_t da = sw + (sl * STAGE_WORDS + lrow * BK + stx) * 4;
        uint32_t db = sw + (sl * STAGE_WORDS + A_WORDS + lrow * BK + stx) * 4;

        #pragma unroll
        for (int ks = 0; ks < 4; ks++) {
            uint32_t kA = (uint32_t)(((ks * 8 + aKoff) ^ swz) * 4);
            uint32_t kB = (uint32_t)(((ks * 8 + bKoff) ^ swz) * 4);
            uint32_t afr[4][4], bfr[8][2];
            #pragma unroll
            for (int mi = 0; mi < 4; mi++)
                ldsm4(afr[mi][0], afr[mi][1], afr[mi][2], afr[mi][3],
                      sA + aBase[mi] + kA);
            #pragma unroll
            for (int p = 0; p < 4; p++)
                ldsm4(bfr[2 * p][0], bfr[2 * p][1], bfr[2 * p + 1][0],
                      bfr[2 * p + 1][1], sB + bBase[p] + kB);
            #pragma unroll
            for (int mi = 0; mi < 4; mi++)
                #pragma unroll
                for (int ni = 0; ni < 8; ni++)
                    mma_tf32(acc[mi][ni], afr[mi], bfr[ni]);

            // de-burst: split next-stage issue across ks=0 and ks=1
            if (ks == 0) {
                if (doLoad) {
                    #pragma unroll
                    for (int it = 0; it < 4; it++)
                        cpa16(da + it * (32 * BK * 4),
                              ybase + nk * BK + (size_t)it * 32 * MDIM);
                    #pragma unroll
                    for (int it = 0; it < 4; it++)
                        cpa16(db + it * (32 * BK * 4),
                              wbase + nk * BK + (size_t)it * 32 * MDIM);
                }
            } else if (ks == 1) {
                if (doLoad) {
                    #pragma unroll
                    for (int it = 4; it < 8; it++)
                        cpa16(db + it * (32 * BK * 4),
                              wbase + nk * BK + (size_t)it * 32 * MDIM);
                }
                CP_COMMIT();
            }
        }

        if (++sc == NSTAGES) sc = 0;
        if (++sl == NSTAGES) sl = 0;
    }

    // ---- epilogue: left rotation + scale + bias, from registers ----
    #pragma unroll
    for (int ni = 0; ni < 8; ni++) {
        int lc = wn + ni * 8 + 2 * t;   // local even col
        float cl = cL_s[lc >> 1], sl_ = sL_s[lc >> 1];
        float s0 = scale_s[lc], s1 = scale_s[lc + 1];
        float bb0 = bias_s[lc], bb1 = bias_s[lc + 1];
        int col = bn + lc;
        #pragma unroll
        for (int mi = 0; mi < 4; mi++) {
            int row = bm + wm + mi * 16 + g;
            float c0 = acc[mi][ni][0], c1 = acc[mi][ni][1];
            float2 o0;
            o0.x = s0 * (cl * c0 - sl_ * c1) + bb0;
            o0.y = s1 * (sl_ * c0 + cl * c1) + bb1;
            *(float2*)(out + (size_t)row * NDIM + col) = o0;
            float c2 = acc[mi][ni][2], c3 = acc[mi][ni][3];
            float2 o1;
            o1.x = s0 * (cl * c2 - sl_ * c3) + bb0;
            o1.y = s1 * (sl_ * c2 + cl * c3) + bb1;
            *(float2*)(out + (size_t)(row + 8) * NDIM + col) = o1;
        }
    }
}

// ---------------------------------------------------------------------------
// Launch. inputs: 0:x 1:W 2:bias 3:theta_L 4:theta_R 5:ecd 6:pairs_L 7:pairs_R
// ---------------------------------------------------------------------------
extern "C" void kernel_launch(void* const* d_in, const int* in_sizes, int n_in,
                              void* d_out, int out_size) {
    const float* x = (const float*)d_in[0];
    const float* W = (const float*)d_in[1];
    const float* bias = (const float*)d_in[2];
    const float* thL = (const float*)d_in[3];
    const float* thR = (const float*)d_in[4];
    const float* ecd = (const float*)d_in[5];
    float* out = (float*)d_out;

    cudaFuncSetAttribute(gemm_kernel, cudaFuncAttributeMaxDynamicSharedMemorySize,
                         SMEM_BYTES);

    scale_kernel<<<SP, 256>>>(W, ecd, thL, thR);
    xrot_kernel<<<(TOKENS * MDIM / 4) / 256, 256>>>(x);

    dim3 grid(NDIM / BN, TOKENS / BM);  // 16 x 16 = 256 CTAs
    gemm_kernel<<<grid, NTHREADS, SMEM_BYTES>>>(bias, out);
}

// round 16
// speedup vs baseline: 1.0569x; 1.0569x over previous
#include <cuda_runtime.h>
#include <cstdint>

#define TOKENS 2048
#define NDIM 4096
#define MDIM 4096
#define SP 2048
#define EPSV 1e-8f

#define BM 128
#define BN 256
#define BK 32
#define NSTAGES 4
#define NTHREADS 256

#define A_WORDS (BM * BK)                 // 4096
#define B_WORDS (BN * BK)                 // 8192
#define STAGE_WORDS (A_WORDS + B_WORDS)   // 12288 = 48KB
#define COEF_WORDS (BN + BN + BN / 2 + BN / 2)
#define SMEM_BYTES ((NSTAGES * STAGE_WORDS + COEF_WORDS) * 4)  // ~195.5KB

// Scratch (device globals; runtime allocation forbidden)
__device__ float g_Wr[(size_t)NDIM * MDIM];   // RNA-rounded W
__device__ float g_y[(size_t)TOKENS * MDIM];  // RNA-rounded right-rotated x
__device__ float g_cL[SP], g_sL[SP], g_cR[SP], g_sR[SP];
__device__ float g_scale[NDIM];

// ---------------------------------------------------------------------------
__device__ __forceinline__ uint32_t f2tf32(float x) {
    uint32_t u;
    asm("cvt.rna.tf32.f32 %0, %1;" : "=r"(u) : "f"(x));
    return u;
}
__device__ __forceinline__ uint32_t smem_u32(const void* p) {
    uint32_t a;
    asm("{ .reg .u64 t; cvta.to.shared.u64 t, %1; cvt.u32.u64 %0, t; }" : "=r"(a) : "l"(p));
    return a;
}
__device__ __forceinline__ void cpa16(uint32_t dst, const float* src) {
    asm volatile("cp.async.cg.shared.global [%0], [%1], 16;" :: "r"(dst), "l"(src) : "memory");
}
#define CP_COMMIT() asm volatile("cp.async.commit_group;" ::: "memory")
#define CP_WAIT2()  asm volatile("cp.async.wait_group 2;" ::: "memory")

__device__ __forceinline__ void mma_tf32(float* c, const uint32_t* a, const uint32_t* b) {
    asm volatile(
        "mma.sync.aligned.m16n8k8.row.col.f32.tf32.tf32.f32 "
        "{%0,%1,%2,%3}, {%4,%5,%6,%7}, {%8,%9}, {%0,%1,%2,%3};\n"
        : "+f"(c[0]), "+f"(c[1]), "+f"(c[2]), "+f"(c[3])
        : "r"(a[0]), "r"(a[1]), "r"(a[2]), "r"(a[3]), "r"(b[0]), "r"(b[1]));
}
__device__ __forceinline__ void ldsm4(uint32_t& r0, uint32_t& r1, uint32_t& r2,
                                      uint32_t& r3, uint32_t addr) {
    asm volatile(
        "ldmatrix.sync.aligned.m8n8.x4.shared.b16 {%0,%1,%2,%3}, [%4];"
        : "=r"(r0), "=r"(r1), "=r"(r2), "=r"(r3) : "r"(addr));
}

// ---------------------------------------------------------------------------
// Kernel 1: per-pair row scales + RNA-rounded W copy + sincos, one pass.
// (R13 form — measured 23.4us @ 47% DRAM; the R15 "streaming" variant was
// slower, reverted.)
// ---------------------------------------------------------------------------
__global__ __launch_bounds__(256) void scale_kernel(
    const float* __restrict__ W, const float* __restrict__ ecd,
    const float* __restrict__ thL, const float* __restrict__ thR) {
    int k = blockIdx.x;
    int i = 2 * k, j = 2 * k + 1;
    if (threadIdx.x == 32) {
        g_cR[k] = cosf(thR[k]);
        g_sR[k] = sinf(thR[k]);
    }
    const float* ri = W + (size_t)i * MDIM;
    const float* rj = W + (size_t)j * MDIM;
    float* wi = g_Wr + (size_t)i * MDIM;
    float* wj = g_Wr + (size_t)j * MDIM;

    float ni = 0.f, nj = 0.f, dd = 0.f;
    for (int c = threadIdx.x * 4; c < MDIM; c += blockDim.x * 4) {
        float4 a = *(const float4*)(ri + c);
        float4 b = *(const float4*)(rj + c);
        ni += a.x * a.x + a.y * a.y + a.z * a.z + a.w * a.w;
        nj += b.x * b.x + b.y * b.y + b.z * b.z + b.w * b.w;
        dd += a.x * b.x + a.y * b.y + a.z * b.z + a.w * b.w;
        float4 ra, rb;
        ra.x = __uint_as_float(f2tf32(a.x)); ra.y = __uint_as_float(f2tf32(a.y));
        ra.z = __uint_as_float(f2tf32(a.z)); ra.w = __uint_as_float(f2tf32(a.w));
        rb.x = __uint_as_float(f2tf32(b.x)); rb.y = __uint_as_float(f2tf32(b.y));
        rb.z = __uint_as_float(f2tf32(b.z)); rb.w = __uint_as_float(f2tf32(b.w));
        *(float4*)(wi + c) = ra;
        *(float4*)(wj + c) = rb;
    }
    #pragma unroll
    for (int off = 16; off; off >>= 1) {
        ni += __shfl_down_sync(0xFFFFFFFFu, ni, off);
        nj += __shfl_down_sync(0xFFFFFFFFu, nj, off);
        dd += __shfl_down_sync(0xFFFFFFFFu, dd, off);
    }
    __shared__ float sm[3][8];
    int w = threadIdx.x >> 5;
    if ((threadIdx.x & 31) == 0) { sm[0][w] = ni; sm[1][w] = nj; sm[2][w] = dd; }
    __syncthreads();
    if (threadIdx.x == 0) {
        ni = 0.f; nj = 0.f; dd = 0.f;
        #pragma unroll
        for (int q = 0; q < 8; q++) { ni += sm[0][q]; nj += sm[1][q]; dd += sm[2][q]; }
        float c = cosf(thL[k]), s = sinf(thL[k]);
        g_cL[k] = c; g_sL[k] = s;
        float ri2 = c * c * ni + s * s * nj - 2.f * c * s * dd;
        float rj2 = s * s * ni + c * c * nj + 2.f * c * s * dd;
        g_scale[i] = sqrtf(ni) * expf(ecd[i]) / (sqrtf(fmaxf(ri2, 0.f)) + EPSV);
        g_scale[j] = sqrtf(nj) * expf(ecd[j]) / (sqrtf(fmaxf(rj2, 0.f)) + EPSV);
    }
}

// ---------------------------------------------------------------------------
// Kernel 2: y = right-rotate(x) with RNA rounding.
// ---------------------------------------------------------------------------
__global__ __launch_bounds__(256) void xrot_kernel(const float* __restrict__ x) {
    int idx = blockIdx.x * blockDim.x + threadIdx.x;   // per float4
    int c4 = (idx * 4) & (MDIM - 1);
    int b0 = c4 >> 1;
    float4 v = *(const float4*)(x + (size_t)idx * 4);
    float c0 = g_cR[b0], s0 = g_sR[b0];
    float c1 = g_cR[b0 + 1], s1 = g_sR[b0 + 1];
    float4 o;
    o.x = __uint_as_float(f2tf32(c0 * v.x + s0 * v.y));
    o.y = __uint_as_float(f2tf32(-s0 * v.x + c0 * v.y));
    o.z = __uint_as_float(f2tf32(c1 * v.z + s1 * v.w));
    o.w = __uint_as_float(f2tf32(-s1 * v.z + c1 * v.w));
    *(float4*)(g_y + (size_t)idx * 4) = o;
}

// ---------------------------------------------------------------------------
// Kernel 3: GEMM out = epilogue( y @ Wr^T ).
// CTA 128x256, BK=32, 256 threads: 8 warps in 2x4, warp tile 64x64.
// 4-stage cp.async pipeline (48KB/stage = 192KB), wait_group 2; single
// cp.async burst + commit after ks=0's MMAs (R13 schedule, measured best).
// NEW vs R13: fragment double-buffering — ks+1's 8 LDSM are issued while
// ks's 32 MMAs execute, hiding the LDSM->MMA dependency latency at the
// head of each ks group (+32 fragment regs, ~250 total, no spill).
// Epilogue: left rotation over adjacent output col pairs + scale + bias.
// ---------------------------------------------------------------------------
__global__ __launch_bounds__(NTHREADS, 1) void gemm_kernel(
    const float* __restrict__ bias, float* __restrict__ out) {
    extern __shared__ uint32_t smw[];
    float* scale_s = (float*)(smw + NSTAGES * STAGE_WORDS);
    float* bias_s = scale_s + BN;
    float* cL_s = bias_s + BN;
    float* sL_s = cL_s + BN / 2;

    int tid = threadIdx.x;
    int bm = blockIdx.y * BM;
    int bn = blockIdx.x * BN;

    // stage epilogue coefficients (visible after first __syncthreads in loop)
    {
        scale_s[tid] = g_scale[bn + tid];
        bias_s[tid] = bias[bn + tid];
        if (tid < BN / 2) {
            cL_s[tid] = g_cL[(bn >> 1) + tid];
            sL_s[tid] = g_sL[(bn >> 1) + tid];
        }
    }

    // loader mapping: 32 rows x 8 x 16B per round (A: 4 rounds, B: 8 rounds)
    int lrow = tid >> 3;              // 0..31
    int lc4 = (tid & 7) * 4;          // 0..28
    int stx = lc4 ^ ((lrow & 7) * 4); // swizzled word offset within 32-word row
    uint32_t sw = smem_u32(smw);

    const float* ybase = g_y + (size_t)(bm + lrow) * MDIM + lc4;
    const float* wbase = g_Wr + (size_t)(bn + lrow) * MDIM + lc4;

    int warp = tid >> 5, lane = tid & 31;
    int g = lane >> 2, t = lane & 3;
    int wm = (warp >> 2) * 64;        // 0,64
    int wn = (warp & 3) * 64;         // 0,64,128,192

    // ldmatrix lane-address precompute
    int sub = lane >> 3, r = lane & 7;
    int swz = 4 * r;
    int aKoff = (sub >> 1) * 4;
    int bKoff = (sub & 1) * 4;
    uint32_t aBase[4], bBase[4];
    {
        int aRow = wm + (sub & 1) * 8 + r;
        #pragma unroll
        for (int mi = 0; mi < 4; mi++)
            aBase[mi] = (uint32_t)(aRow + 16 * mi) * (BK * 4);
        int bGrp = sub >> 1;               // 0 or 1
        #pragma unroll
        for (int p = 0; p < 4; p++)
            bBase[p] = (uint32_t)(wn + 8 * (2 * p + bGrp) + r) * (BK * 4);
    }

    float acc[4][8][4];
    #pragma unroll
    for (int mi = 0; mi < 4; mi++)
        #pragma unroll
        for (int ni = 0; ni < 8; ni++)
            #pragma unroll
            for (int q = 0; q < 4; q++) acc[mi][ni][q] = 0.f;

    const int NKT = MDIM / BK;  // 128

    // prologue: stages 0..2
    #pragma unroll
    for (int s = 0; s < NSTAGES - 1; s++) {
        uint32_t da = sw + (s * STAGE_WORDS + lrow * BK + stx) * 4;
        #pragma unroll
        for (int it = 0; it < 4; it++)
            cpa16(da + it * (32 * BK * 4), ybase + s * BK + (size_t)it * 32 * MDIM);
        uint32_t db = sw + (s * STAGE_WORDS + A_WORDS + lrow * BK + stx) * 4;
        #pragma unroll
        for (int it = 0; it < 8; it++)
            cpa16(db + it * (32 * BK * 4), wbase + s * BK + (size_t)it * 32 * MDIM);
        CP_COMMIT();
    }

    int sc = 0, sl = NSTAGES - 1;
    #pragma unroll 1
    for (int kt = 0; kt < NKT; kt++) {
        CP_WAIT2();
        __syncthreads();

        uint32_t sA = sw + (uint32_t)sc * (STAGE_WORDS * 4);
        uint32_t sB = sA + A_WORDS * 4;

        uint32_t afr[2][4][4], bfr[2][8][2];

        // preload ks=0 fragments into slot 0
        {
            uint32_t kA = (uint32_t)(((0 + aKoff) ^ swz) * 4);
            uint32_t kB = (uint32_t)(((0 + bKoff) ^ swz) * 4);
            #pragma unroll
            for (int mi = 0; mi < 4; mi++)
                ldsm4(afr[0][mi][0], afr[0][mi][1], afr[0][mi][2], afr[0][mi][3],
                      sA + aBase[mi] + kA);
            #pragma unroll
            for (int p = 0; p < 4; p++)
                ldsm4(bfr[0][2 * p][0], bfr[0][2 * p][1], bfr[0][2 * p + 1][0],
                      bfr[0][2 * p + 1][1], sB + bBase[p] + kB);
        }

        #pragma unroll
        for (int ks = 0; ks < 4; ks++) {
            int cur = ks & 1, nxt = cur ^ 1;
            // prefetch next ks group's fragments (overlaps with MMAs below)
            if (ks < 3) {
                uint32_t kA = (uint32_t)((((ks + 1) * 8 + aKoff) ^ swz) * 4);
                uint32_t kB = (uint32_t)((((ks + 1) * 8 + bKoff) ^ swz) * 4);
                #pragma unroll
                for (int mi = 0; mi < 4; mi++)
                    ldsm4(afr[nxt][mi][0], afr[nxt][mi][1], afr[nxt][mi][2],
                          afr[nxt][mi][3], sA + aBase[mi] + kA);
                #pragma unroll
                for (int p = 0; p < 4; p++)
                    ldsm4(bfr[nxt][2 * p][0], bfr[nxt][2 * p][1],
                          bfr[nxt][2 * p + 1][0], bfr[nxt][2 * p + 1][1],
                          sB + bBase[p] + kB);
            }

            #pragma unroll
            for (int mi = 0; mi < 4; mi++)
                #pragma unroll
                for (int ni = 0; ni < 8; ni++)
                    mma_tf32(acc[mi][ni], afr[cur][mi], bfr[cur][ni]);

            // R13 schedule: full next-stage burst + commit after ks=0's MMAs
            if (ks == 0) {
                int nk = kt + NSTAGES - 1;
                if (nk < NKT) {
                    uint32_t da = sw + (sl * STAGE_WORDS + lrow * BK + stx) * 4;
                    #pragma unroll
                    for (int it = 0; it < 4; it++)
                        cpa16(da + it * (32 * BK * 4),
                              ybase + nk * BK + (size_t)it * 32 * MDIM);
                    uint32_t db = sw + (sl * STAGE_WORDS + A_WORDS + lrow * BK + stx) * 4;
                    #pragma unroll
                    for (int it = 0; it < 8; it++)
                        cpa16(db + it * (32 * BK * 4),
                              wbase + nk * BK + (size_t)it * 32 * MDIM);
                }
                CP_COMMIT();
            }
        }

        if (++sc == NSTAGES) sc = 0;
        if (++sl == NSTAGES) sl = 0;
    }

    // ---- epilogue: left rotation + scale + bias, from registers ----
    #pragma unroll
    for (int ni = 0; ni < 8; ni++) {
        int lc = wn + ni * 8 + 2 * t;   // local even col
        float cl = cL_s[lc >> 1], sl_ = sL_s[lc >> 1];
        float s0 = scale_s[lc], s1 = scale_s[lc + 1];
        float bb0 = bias_s[lc], bb1 = bias_s[lc + 1];
        int col = bn + lc;
        #pragma unroll
        for (int mi = 0; mi < 4; mi++) {
            int row = bm + wm + mi * 16 + g;
            float c0 = acc[mi][ni][0], c1 = acc[mi][ni][1];
            float2 o0;
            o0.x = s0 * (cl * c0 - sl_ * c1) + bb0;
            o0.y = s1 * (sl_ * c0 + cl * c1) + bb1;
            *(float2*)(out + (size_t)row * NDIM + col) = o0;
            float c2 = acc[mi][ni][2], c3 = acc[mi][ni][3];
            float2 o1;
            o1.x = s0 * (cl * c2 - sl_ * c3) + bb0;
            o1.y = s1 * (sl_ * c2 + cl * c3) + bb1;
            *(float2*)(out + (size_t)(row + 8) * NDIM + col) = o1;
        }
    }
}

// ---------------------------------------------------------------------------
// Launch. inputs: 0:x 1:W 2:bias 3:theta_L 4:theta_R 5:ecd 6:pairs_L 7:pairs_R
// ---------------------------------------------------------------------------
extern "C" void kernel_launch(void* const* d_in, const int* in_sizes, int n_in,
                              void* d_out, int out_size) {
    const float* x = (const float*)d_in[0];
    const float* W = (const float*)d_in[1];
    const float* bias = (const float*)d_in[2];
    const float* thL = (const float*)d_in[3];
    const float* thR = (const float*)d_in[4];
    const float* ecd = (const float*)d_in[5];
    float* out = (float*)d_out;

    cudaFuncSetAttribute(gemm_kernel, cudaFuncAttributeMaxDynamicSharedMemorySize,
                         SMEM_BYTES);

    scale_kernel<<<SP, 256>>>(W, ecd, thL, thR);
    xrot_kernel<<<(TOKENS * MDIM / 4) / 256, 256>>>(x);

    dim3 grid(NDIM / BN, TOKENS / BM);  // 16 x 16 = 256 CTAs
    gemm_kernel<<<grid, NTHREADS, SMEM_BYTES>>>(bias, out);
}

// round 17
// speedup vs baseline: 1.0944x; 1.0354x over previous
#include <cuda_runtime.h>
#include <cstdint>

#define TOKENS 2048
#define NDIM 4096
#define MDIM 4096
#define SP 2048
#define EPSV 1e-8f

#define BM 128
#define BN 256
#define BK 32
#define NSTAGES 4
#define NTHREADS 256

#define A_WORDS (BM * BK)                 // 4096
#define B_WORDS (BN * BK)                 // 8192
#define STAGE_WORDS (A_WORDS + B_WORDS)   // 12288 = 48KB
#define COEF_WORDS (BN + BN + BN / 2 + BN / 2)
#define SMEM_BYTES ((NSTAGES * STAGE_WORDS + COEF_WORDS) * 4)  // ~195.5KB

// Truncation-bias compensation: mma.sync truncates the raw-fp32 A operand to
// tf32 (drops 13 mantissa bits), shrinking |x| by mean 2^-11*ln2 ~= 3.38e-4.
#define TRUNC_COMP 1.000338f

// Scratch (device globals; runtime allocation forbidden)
__device__ float g_Wr[(size_t)NDIM * MDIM];   // RNA-rounded, right-rotated W
__device__ float g_cL[SP], g_sL[SP];
__device__ float g_scale[NDIM];

// ---------------------------------------------------------------------------
__device__ __forceinline__ uint32_t f2tf32(float x) {
    uint32_t u;
    asm("cvt.rna.tf32.f32 %0, %1;" : "=r"(u) : "f"(x));
    return u;
}
__device__ __forceinline__ uint32_t smem_u32(const void* p) {
    uint32_t a;
    asm("{ .reg .u64 t; cvta.to.shared.u64 t, %1; cvt.u32.u64 %0, t; }" : "=r"(a) : "l"(p));
    return a;
}
__device__ __forceinline__ void cpa16(uint32_t dst, const float* src) {
    asm volatile("cp.async.cg.shared.global [%0], [%1], 16;" :: "r"(dst), "l"(src) : "memory");
}
#define CP_COMMIT() asm volatile("cp.async.commit_group;" ::: "memory")
#define CP_WAIT2()  asm volatile("cp.async.wait_group 2;" ::: "memory")

__device__ __forceinline__ void mma_tf32(float* c, const uint32_t* a, const uint32_t* b) {
    asm volatile(
        "mma.sync.aligned.m16n8k8.row.col.f32.tf32.tf32.f32 "
        "{%0,%1,%2,%3}, {%4,%5,%6,%7}, {%8,%9}, {%0,%1,%2,%3};\n"
        : "+f"(c[0]), "+f"(c[1]), "+f"(c[2]), "+f"(c[3])
        : "r"(a[0]), "r"(a[1]), "r"(a[2]), "r"(a[3]), "r"(b[0]), "r"(b[1]));
}
__device__ __forceinline__ void ldsm4(uint32_t& r0, uint32_t& r1, uint32_t& r2,
                                      uint32_t& r3, uint32_t addr) {
    asm volatile(
        "ldmatrix.sync.aligned.m8n8.x4.shared.b16 {%0,%1,%2,%3}, [%4];"
        : "=r"(r0), "=r"(r1), "=r"(r2), "=r"(r3) : "r"(addr));
}

// ---------------------------------------------------------------------------
// Kernel 1: per-pair row scales + right-rotated + RNA-rounded W, one pass.
// Block k handles row pair (2k, 2k+1).
//  - ni/nj/dd computed on the ORIGINAL rows (right rotation is orthogonal on
//    columns, so row norms and dot products are invariant — formulas hold).
//  - NEW: the right rotation G is folded into W's columns here:
//      W2[:,p] = c*W[:,p] - s*W[:,q],  W2[:,q] = s*W[:,p] + c*W[:,q]
//    (out = x (W G)^T L^T diag(s); A operand becomes RAW x, no x prepass).
//  - scale carries TRUNC_COMP to cancel the A-operand tf32-truncation bias.
// ---------------------------------------------------------------------------
__global__ __launch_bounds__(256) void scale_kernel(
    const float* __restrict__ W, const float* __restrict__ ecd,
    const float* __restrict__ thL, const float* __restrict__ thR) {
    int k = blockIdx.x;
    int i = 2 * k, j = 2 * k + 1;
    const float* ri = W + (size_t)i * MDIM;
    const float* rj = W + (size_t)j * MDIM;
    float* wi = g_Wr + (size_t)i * MDIM;
    float* wj = g_Wr + (size_t)j * MDIM;

    float ni = 0.f, nj = 0.f, dd = 0.f;
    for (int c = threadIdx.x * 4; c < MDIM; c += blockDim.x * 4) {
        float4 a = *(const float4*)(ri + c);
        float4 b = *(const float4*)(rj + c);
        ni += a.x * a.x + a.y * a.y + a.z * a.z + a.w * a.w;
        nj += b.x * b.x + b.y * b.y + b.z * b.z + b.w * b.w;
        dd += a.x * b.x + a.y * b.y + a.z * b.z + a.w * b.w;

        // right rotation of column pairs (c,c+1) and (c+2,c+3)
        float s0, c0, s1, c1;
        __sincosf(thR[c >> 1], &s0, &c0);
        __sincosf((c >> 1) + 1 < SP ? thR[(c >> 1) + 1] : 0.f, &s1, &c1);
        float4 ra, rb;
        ra.x = __uint_as_float(f2tf32(c0 * a.x - s0 * a.y));
        ra.y = __uint_as_float(f2tf32(s0 * a.x + c0 * a.y));
        ra.z = __uint_as_float(f2tf32(c1 * a.z - s1 * a.w));
        ra.w = __uint_as_float(f2tf32(s1 * a.z + c1 * a.w));
        rb.x = __uint_as_float(f2tf32(c0 * b.x - s0 * b.y));
        rb.y = __uint_as_float(f2tf32(s0 * b.x + c0 * b.y));
        rb.z = __uint_as_float(f2tf32(c1 * b.z - s1 * b.w));
        rb.w = __uint_as_float(f2tf32(s1 * b.z + c1 * b.w));
        *(float4*)(wi + c) = ra;
        *(float4*)(wj + c) = rb;
    }
    #pragma unroll
    for (int off = 16; off; off >>= 1) {
        ni += __shfl_down_sync(0xFFFFFFFFu, ni, off);
        nj += __shfl_down_sync(0xFFFFFFFFu, nj, off);
        dd += __shfl_down_sync(0xFFFFFFFFu, dd, off);
    }
    __shared__ float sm[3][8];
    int w = threadIdx.x >> 5;
    if ((threadIdx.x & 31) == 0) { sm[0][w] = ni; sm[1][w] = nj; sm[2][w] = dd; }
    __syncthreads();
    if (threadIdx.x == 0) {
        ni = 0.f; nj = 0.f; dd = 0.f;
        #pragma unroll
        for (int q = 0; q < 8; q++) { ni += sm[0][q]; nj += sm[1][q]; dd += sm[2][q]; }
        float c = cosf(thL[k]), s = sinf(thL[k]);
        g_cL[k] = c; g_sL[k] = s;
        float ri2 = c * c * ni + s * s * nj - 2.f * c * s * dd;
        float rj2 = s * s * ni + c * c * nj + 2.f * c * s * dd;
        g_scale[i] = TRUNC_COMP * sqrtf(ni) * expf(ecd[i]) / (sqrtf(fmaxf(ri2, 0.f)) + EPSV);
        g_scale[j] = TRUNC_COMP * sqrtf(nj) * expf(ecd[j]) / (sqrtf(fmaxf(rj2, 0.f)) + EPSV);
    }
}

// ---------------------------------------------------------------------------
// Kernel 2: GEMM out = epilogue( x @ g_Wr^T )  (A = RAW x, HW-truncated).
// CTA 128x256, BK=32, 256 threads: 8 warps in 2x4, warp tile 64x64.
// 4-stage cp.async pipeline (48KB/stage = 192KB), wait_group 2; single
// cp.async burst + commit after ks=0's MMAs; fragment double-buffering
// (ks+1's 8 LDSM overlap ks's 32 MMAs). R16 structure, A reads x directly.
// Epilogue: left rotation over adjacent output col pairs + scale + bias.
// ---------------------------------------------------------------------------
__global__ __launch_bounds__(NTHREADS, 1) void gemm_kernel(
    const float* __restrict__ x,
    const float* __restrict__ bias, float* __restrict__ out) {
    extern __shared__ uint32_t smw[];
    float* scale_s = (float*)(smw + NSTAGES * STAGE_WORDS);
    float* bias_s = scale_s + BN;
    float* cL_s = bias_s + BN;
    float* sL_s = cL_s + BN / 2;

    int tid = threadIdx.x;
    int bm = blockIdx.y * BM;
    int bn = blockIdx.x * BN;

    // stage epilogue coefficients (visible after first __syncthreads in loop)
    {
        scale_s[tid] = g_scale[bn + tid];
        bias_s[tid] = bias[bn + tid];
        if (tid < BN / 2) {
            cL_s[tid] = g_cL[(bn >> 1) + tid];
            sL_s[tid] = g_sL[(bn >> 1) + tid];
        }
    }

    // loader mapping: 32 rows x 8 x 16B per round (A: 4 rounds, B: 8 rounds)
    int lrow = tid >> 3;              // 0..31
    int lc4 = (tid & 7) * 4;          // 0..28
    int stx = lc4 ^ ((lrow & 7) * 4); // swizzled word offset within 32-word row
    uint32_t sw = smem_u32(smw);

    const float* ybase = x + (size_t)(bm + lrow) * MDIM + lc4;
    const float* wbase = g_Wr + (size_t)(bn + lrow) * MDIM + lc4;

    int warp = tid >> 5, lane = tid & 31;
    int g = lane >> 2, t = lane & 3;
    int wm = (warp >> 2) * 64;        // 0,64
    int wn = (warp & 3) * 64;         // 0,64,128,192

    // ldmatrix lane-address precompute
    int sub = lane >> 3, r = lane & 7;
    int swz = 4 * r;
    int aKoff = (sub >> 1) * 4;
    int bKoff = (sub & 1) * 4;
    uint32_t aBase[4], bBase[4];
    {
        int aRow = wm + (sub & 1) * 8 + r;
        #pragma unroll
        for (int mi = 0; mi < 4; mi++)
            aBase[mi] = (uint32_t)(aRow + 16 * mi) * (BK * 4);
        int bGrp = sub >> 1;               // 0 or 1
        #pragma unroll
        for (int p = 0; p < 4; p++)
            bBase[p] = (uint32_t)(wn + 8 * (2 * p + bGrp) + r) * (BK * 4);
    }

    float acc[4][8][4];
    #pragma unroll
    for (int mi = 0; mi < 4; mi++)
        #pragma unroll
        for (int ni = 0; ni < 8; ni++)
            #pragma unroll
            for (int q = 0; q < 4; q++) acc[mi][ni][q] = 0.f;

    const int NKT = MDIM / BK;  // 128

    // prologue: stages 0..2
    #pragma unroll
    for (int s = 0; s < NSTAGES - 1; s++) {
        uint32_t da = sw + (s * STAGE_WORDS + lrow * BK + stx) * 4;
        #pragma unroll
        for (int it = 0; it < 4; it++)
            cpa16(da + it * (32 * BK * 4), ybase + s * BK + (size_t)it * 32 * MDIM);
        uint32_t db = sw + (s * STAGE_WORDS + A_WORDS + lrow * BK + stx) * 4;
        #pragma unroll
        for (int it = 0; it < 8; it++)
            cpa16(db + it * (32 * BK * 4), wbase + s * BK + (size_t)it * 32 * MDIM);
        CP_COMMIT();
    }

    int sc = 0, sl = NSTAGES - 1;
    #pragma unroll 1
    for (int kt = 0; kt < NKT; kt++) {
        CP_WAIT2();
        __syncthreads();

        uint32_t sA = sw + (uint32_t)sc * (STAGE_WORDS * 4);
        uint32_t sB = sA + A_WORDS * 4;

        uint32_t afr[2][4][4], bfr[2][8][2];

        // preload ks=0 fragments into slot 0
        {
            uint32_t kA = (uint32_t)(((0 + aKoff) ^ swz) * 4);
            uint32_t kB = (uint32_t)(((0 + bKoff) ^ swz) * 4);
            #pragma unroll
            for (int mi = 0; mi < 4; mi++)
                ldsm4(afr[0][mi][0], afr[0][mi][1], afr[0][mi][2], afr[0][mi][3],
                      sA + aBase[mi] + kA);
            #pragma unroll
            for (int p = 0; p < 4; p++)
                ldsm4(bfr[0][2 * p][0], bfr[0][2 * p][1], bfr[0][2 * p + 1][0],
                      bfr[0][2 * p + 1][1], sB + bBase[p] + kB);
        }

        #pragma unroll
        for (int ks = 0; ks < 4; ks++) {
            int cur = ks & 1, nxt = cur ^ 1;
            // prefetch next ks group's fragments (overlaps with MMAs below)
            if (ks < 3) {
                uint32_t kA = (uint32_t)((((ks + 1) * 8 + aKoff) ^ swz) * 4);
                uint32_t kB = (uint32_t)((((ks + 1) * 8 + bKoff) ^ swz) * 4);
                #pragma unroll
                for (int mi = 0; mi < 4; mi++)
                    ldsm4(afr[nxt][mi][0], afr[nxt][mi][1], afr[nxt][mi][2],
                          afr[nxt][mi][3], sA + aBase[mi] + kA);
                #pragma unroll
                for (int p = 0; p < 4; p++)
                    ldsm4(bfr[nxt][2 * p][0], bfr[nxt][2 * p][1],
                          bfr[nxt][2 * p + 1][0], bfr[nxt][2 * p + 1][1],
                          sB + bBase[p] + kB);
            }

            #pragma unroll
            for (int mi = 0; mi < 4; mi++)
                #pragma unroll
                for (int ni = 0; ni < 8; ni++)
                    mma_tf32(acc[mi][ni], afr[cur][mi], bfr[cur][ni]);

            // full next-stage burst + commit after ks=0's MMAs
            if (ks == 0) {
                int nk = kt + NSTAGES - 1;
                if (nk < NKT) {
                    uint32_t da = sw + (sl * STAGE_WORDS + lrow * BK + stx) * 4;
                    #pragma unroll
                    for (int it = 0; it < 4; it++)
                        cpa16(da + it * (32 * BK * 4),
                              ybase + nk * BK + (size_t)it * 32 * MDIM);
                    uint32_t db = sw + (sl * STAGE_WORDS + A_WORDS + lrow * BK + stx) * 4;
                    #pragma unroll
                    for (int it = 0; it < 8; it++)
                        cpa16(db + it * (32 * BK * 4),
                              wbase + nk * BK + (size_t)it * 32 * MDIM);
                }
                CP_COMMIT();
            }
        }

        if (++sc == NSTAGES) sc = 0;
        if (++sl == NSTAGES) sl = 0;
    }

    // ---- epilogue: left rotation + scale + bias, from registers ----
    #pragma unroll
    for (int ni = 0; ni < 8; ni++) {
        int lc = wn + ni * 8 + 2 * t;   // local even col
        float cl = cL_s[lc >> 1], sl_ = sL_s[lc >> 1];
        float s0 = scale_s[lc], s1 = scale_s[lc + 1];
        float bb0 = bias_s[lc], bb1 = bias_s[lc + 1];
        int col = bn + lc;
        #pragma unroll
        for (int mi = 0; mi < 4; mi++) {
            int row = bm + wm + mi * 16 + g;
            float c0 = acc[mi][ni][0], c1 = acc[mi][ni][1];
            float2 o0;
            o0.x = s0 * (cl * c0 - sl_ * c1) + bb0;
            o0.y = s1 * (sl_ * c0 + cl * c1) + bb1;
            *(float2*)(out + (size_t)row * NDIM + col) = o0;
            float c2 = acc[mi][ni][2], c3 = acc[mi][ni][3];
            float2 o1;
            o1.x = s0 * (cl * c2 - sl_ * c3) + bb0;
            o1.y = s1 * (sl_ * c2 + cl * c3) + bb1;
            *(float2*)(out + (size_t)(row + 8) * NDIM + col) = o1;
        }
    }
}

// ---------------------------------------------------------------------------
// Launch. inputs: 0:x 1:W 2:bias 3:theta_L 4:theta_R 5:ecd 6:pairs_L 7:pairs_R
// ---------------------------------------------------------------------------
extern "C" void kernel_launch(void* const* d_in, const int* in_sizes, int n_in,
                              void* d_out, int out_size) {
    const float* x = (const float*)d_in[0];
    const float* W = (const float*)d_in[1];
    const float* bias = (const float*)d_in[2];
    const float* thL = (const float*)d_in[3];
    const float* thR = (const float*)d_in[4];
    const float* ecd = (const float*)d_in[5];
    float* out = (float*)d_out;

    cudaFuncSetAttribute(gemm_kernel, cudaFuncAttributeMaxDynamicSharedMemorySize,
                         SMEM_BYTES);

    scale_kernel<<<SP, 256>>>(W, ecd, thL, thR);

    dim3 grid(NDIM / BN, TOKENS / BM);  // 16 x 16 = 256 CTAs
    gemm_kernel<<<grid, NTHREADS, SMEM_BYTES>>>(x, bias, out);
}